// round 12
// baseline (speedup 1.0000x reference)
#include <cuda_runtime.h>
#include <cuda_fp16.h>
#include <cuda_bf16.h>

// ---------------------------------------------------------------------------
// TriplaneEncoder: out[n][c] = sum_{p=0..2} bilinear(C_mat[p], coords_p(n))[c]
// Planes: p0:(x0,x1), p1:(x0,x2), p2:(x1,x2); gx = first (W axis), gy = second (H).
// align_corners=False, zero padding. RES=512, C=32, N=2097152.
//
// R11 (= R9/R10 design; prior rounds died to container infra, not the kernel):
//  - sample: 8 lanes/point. The two x-corners are adjacent 64B records, so one
//    128B row-span covers both; lanes 0-3 carry wx0, lanes 4-7 wx1, shfl_xor(4)
//    combines. 2 row-span loads per plane instead of 4 corner loads -> ~25%
//    fewer L1 wavefronts at identical L2 sector traffic.
//  - transpose: 8B-packed stores (256B/warp contiguous).
// ---------------------------------------------------------------------------

#define RES   512
#define CFEAT 32

// 48 MB pixel-major fp16 table, +64 halves pad for the dead (weight-0) overread
// at bx=511 row-span loads.
__device__ __half g_Th[3 * RES * RES * CFEAT + 64];

// ---------------------------------------------------------------------------
// Transpose+convert: src [p][c][y][x] f32 -> dst [p][y][x][c] f16.
// Block 256. grid = (16, 512, 3).
// ---------------------------------------------------------------------------
__global__ __launch_bounds__(256)
void transpose_kernel(const float* __restrict__ src)
{
    __shared__ float tile[32][33];   // [c][x], padded

    const int p  = blockIdx.z;
    const int y  = blockIdx.y;
    const int x0 = blockIdx.x * 32;
    const int t  = threadIdx.x;          // 0..255
    const int tx = t & 31;
    const int ty = t >> 5;               // 0..7

    // Load 32 channels x 32 x-positions, coalesced along x
    const float* sp = src + ((size_t)p * CFEAT) * (RES * RES) + (size_t)y * RES + x0;
    #pragma unroll
    for (int c = ty; c < 32; c += 8) {
        tile[c][tx] = sp[(size_t)c * (RES * RES) + tx];
    }
    __syncthreads();

    // Store: thread packs 4 channels of one pixel -> 8B (half2 x2).
    // Warp covers 4 pixels x 64B = 256B contiguous.
    const int xi  = t >> 3;              // 0..31 pixel within tile
    const int seg = t & 7;               // 0..7 channel quad

    struct __align__(8) H4 { __half2 a, b; };
    H4 packed;
    packed.a = __floats2half2_rn(tile[4 * seg + 0][xi], tile[4 * seg + 1][xi]);
    packed.b = __floats2half2_rn(tile[4 * seg + 2][xi], tile[4 * seg + 3][xi]);

    __half* dp = g_Th + (((size_t)p * RES + y) * RES + x0) * CFEAT;
    *reinterpret_cast<H4*>(dp + (size_t)xi * CFEAT + seg * 4) = packed;
}

// ---------------------------------------------------------------------------
// Sample kernel: 8 lanes per point.
//   lane l: channel group g = l & 3 (16B of a 64B pixel record);
//   l < 4 -> x0 half of the 128B row-span (weight wA), l >= 4 -> x1 half (wB).
//   Byte offset within span = l * 16.
// ---------------------------------------------------------------------------
__device__ __forceinline__ void accum_span(float acc[8], const __half* __restrict__ ptr, float w)
{
    const uint4 raw = __ldg(reinterpret_cast<const uint4*>(ptr));
    const __half2* h2 = reinterpret_cast<const __half2*>(&raw);
    #pragma unroll
    for (int i = 0; i < 4; ++i) {
        float2 f = __half22float2(h2[i]);
        acc[2 * i + 0] = fmaf(w, f.x, acc[2 * i + 0]);
        acc[2 * i + 1] = fmaf(w, f.y, acc[2 * i + 1]);
    }
}

__global__ __launch_bounds__(256)
void sample_kernel(const float* __restrict__ x, float* __restrict__ out, int npts)
{
    const int gid  = blockIdx.x * blockDim.x + threadIdx.x;
    const int pt   = gid >> 3;
    const int lane = gid & 7;
    if (pt >= npts) return;

    const bool hiX = (lane >= 4);

    // 8 lanes of a point read the same 3 floats -> L1 broadcast
    const float c0 = __ldg(x + (size_t)pt * 3 + 0);
    const float c1 = __ldg(x + (size_t)pt * 3 + 1);
    const float c2 = __ldg(x + (size_t)pt * 3 + 2);

    const float gxs[3] = { c0, c0, c1 };
    const float gys[3] = { c1, c2, c2 };

    float acc[8];
    #pragma unroll
    for (int i = 0; i < 8; ++i) acc[i] = 0.0f;

    #pragma unroll
    for (int p = 0; p < 3; ++p) {
        const float ix = ((gxs[p] + 1.0f) * (float)RES - 1.0f) * 0.5f;
        const float iy = ((gys[p] + 1.0f) * (float)RES - 1.0f) * 0.5f;

        const float x0f = floorf(ix);
        const float y0f = floorf(iy);
        const float wx1 = ix - x0f, wx0 = 1.0f - wx1;
        const float wy1 = iy - y0f, wy0 = 1.0f - wy1;

        const int xi0 = (int)x0f;        // in [-1, 511] since ix in [-0.5, 511.5]
        const int yi0 = (int)y0f;        // in [-1, 511]

        // x span: base pixel bx; lanes 0-3 weight wA (pixel bx), 4-7 wB (pixel bx+1)
        const int   bx = max(xi0, 0);
        const float wA = (xi0 >= 0) ? wx0 : wx1;                 // xi0==-1: base IS the x1 pixel
        const float wB = (xi0 >= 0 && xi0 < RES - 1) ? wx1 : 0.f;
        const float wlx = hiX ? wB : wA;

        // y rows (independent loads)
        const int   rA = max(yi0, 0);
        const float vA = (yi0 >= 0) ? wy0 : 0.f;
        const int   rB = min(yi0 + 1, RES - 1);
        const float vB = (yi0 + 1 <= RES - 1) ? wy1 : 0.f;

        const __half* Tp = g_Th + (size_t)p * (RES * RES * CFEAT) + (size_t)lane * 8;
        accum_span(acc, Tp + ((size_t)rA * RES + bx) * CFEAT, wlx * vA);
        accum_span(acc, Tp + ((size_t)rB * RES + bx) * CFEAT, wlx * vB);
    }

    // Combine x0/x1 halves: lanes l and l^4 hold partials for channel group l&3
    #pragma unroll
    for (int i = 0; i < 8; ++i) {
        acc[i] += __shfl_xor_sync(0xffffffff, acc[i], 4);
    }

    // Output: 128B per point across 8 lanes (16B each), warp writes 512B contiguous.
    const int g = lane & 3;
    float4 v = hiX ? make_float4(acc[4], acc[5], acc[6], acc[7])
                   : make_float4(acc[0], acc[1], acc[2], acc[3]);
    float* optr = out + (size_t)pt * CFEAT + g * 8 + (hiX ? 4 : 0);
    __stwt(reinterpret_cast<float4*>(optr), v);
}

// ---------------------------------------------------------------------------
extern "C" void kernel_launch(void* const* d_in, const int* in_sizes, int n_in,
                              void* d_out, int out_size)
{
    const float* x_in  = (const float*)d_in[0];   // [N, 3]
    const float* c_mat = (const float*)d_in[1];   // [3, 32, 512, 512]
    float* out = (float*)d_out;                   // [N, 32]

    const int npts = in_sizes[0] / 3;

    dim3 tg(RES / 32, RES, 3);
    transpose_kernel<<<tg, 256>>>(c_mat);

    const int threads = 256;
    const long long total = (long long)npts * 8;
    const int blocks = (int)((total + threads - 1) / threads);
    sample_kernel<<<blocks, threads>>>(x_in, out, npts);
}

// round 14
// speedup vs baseline: 1.1183x; 1.1183x over previous
#include <cuda_runtime.h>
#include <cuda_fp16.h>
#include <cuda_bf16.h>

// ---------------------------------------------------------------------------
// TriplaneEncoder: out[n][c] = sum_{p=0..2} bilinear(C_mat[p], coords_p(n))[c]
// Planes: p0:(x0,x1), p1:(x0,x2), p2:(x1,x2); gx = first (W axis), gy = second (H).
// align_corners=False, zero padding. RES=512, C=32, N=2097152.
//
// R13 (= R12 resubmit; R12's bench died to container infra):
//  8 lanes/point span-gather + 2 points per thread.
//  - 8 lanes cover the 128B two-pixel x-span; lanes 0-3 weight wx0, 4-7 wx1;
//    shfl_xor(4) combines -> 6 load instructions per point.
//  - 2 points per thread restores 12 independent in-flight loads (MLP=12),
//    fixing R11's latency-bound regression.
// ---------------------------------------------------------------------------

#define RES   512
#define CFEAT 32

// 48 MB pixel-major fp16 table, +64 halves pad for the dead (weight-0) overread
// at bx=511 hiX span loads.
__device__ __half g_Th[3 * RES * RES * CFEAT + 64];

// ---------------------------------------------------------------------------
// Transpose+convert: src [p][c][y][x] f32 -> dst [p][y][x][c] f16.
// Block 256. grid = (16, 512, 3).
// ---------------------------------------------------------------------------
__global__ __launch_bounds__(256)
void transpose_kernel(const float* __restrict__ src)
{
    __shared__ float tile[32][33];   // [c][x], padded

    const int p  = blockIdx.z;
    const int y  = blockIdx.y;
    const int x0 = blockIdx.x * 32;
    const int t  = threadIdx.x;
    const int tx = t & 31;
    const int ty = t >> 5;

    const float* sp = src + ((size_t)p * CFEAT) * (RES * RES) + (size_t)y * RES + x0;
    #pragma unroll
    for (int c = ty; c < 32; c += 8) {
        tile[c][tx] = sp[(size_t)c * (RES * RES) + tx];
    }
    __syncthreads();

    const int xi  = t >> 3;              // 0..31 pixel within tile
    const int seg = t & 7;               // 0..7 channel quad

    struct __align__(8) H4 { __half2 a, b; };
    H4 packed;
    packed.a = __floats2half2_rn(tile[4 * seg + 0][xi], tile[4 * seg + 1][xi]);
    packed.b = __floats2half2_rn(tile[4 * seg + 2][xi], tile[4 * seg + 3][xi]);

    __half* dp = g_Th + (((size_t)p * RES + y) * RES + x0) * CFEAT;
    *reinterpret_cast<H4*>(dp + (size_t)xi * CFEAT + seg * 4) = packed;
}

// ---------------------------------------------------------------------------
// Sample kernel
// ---------------------------------------------------------------------------
__device__ __forceinline__ void accum_span(float acc[8], const __half* __restrict__ ptr, float w)
{
    const uint4 raw = __ldg(reinterpret_cast<const uint4*>(ptr));
    const __half2* h2 = reinterpret_cast<const __half2*>(&raw);
    #pragma unroll
    for (int i = 0; i < 4; ++i) {
        float2 f = __half22float2(h2[i]);
        acc[2 * i + 0] = fmaf(w, f.x, acc[2 * i + 0]);
        acc[2 * i + 1] = fmaf(w, f.y, acc[2 * i + 1]);
    }
}

// One plane's two row-span loads for one point.
__device__ __forceinline__ void plane_sample(float acc[8], const __half* __restrict__ Tp,
                                             float gx, float gy, bool hiX)
{
    const float ix = ((gx + 1.0f) * (float)RES - 1.0f) * 0.5f;
    const float iy = ((gy + 1.0f) * (float)RES - 1.0f) * 0.5f;

    const float x0f = floorf(ix);
    const float y0f = floorf(iy);
    const float wx1 = ix - x0f, wx0 = 1.0f - wx1;
    const float wy1 = iy - y0f, wy0 = 1.0f - wy1;

    const int xi0 = (int)x0f;            // in [-1, 511]
    const int yi0 = (int)y0f;            // in [-1, 511]

    const int   bx = max(xi0, 0);
    const float wA = (xi0 >= 0) ? wx0 : wx1;                  // xi0==-1: base IS the x1 pixel
    const float wB = (xi0 >= 0 && xi0 < RES - 1) ? wx1 : 0.f;
    const float wlx = hiX ? wB : wA;

    const int   rA = max(yi0, 0);
    const float vA = (yi0 >= 0) ? wy0 : 0.f;
    const int   rB = min(yi0 + 1, RES - 1);
    const float vB = (yi0 + 1 <= RES - 1) ? wy1 : 0.f;

    accum_span(acc, Tp + ((size_t)rA * RES + bx) * CFEAT, wlx * vA);
    accum_span(acc, Tp + ((size_t)rB * RES + bx) * CFEAT, wlx * vB);
}

__global__ __launch_bounds__(256)
void sample_kernel(const float* __restrict__ x, float* __restrict__ out, int half)
{
    const int gid  = blockIdx.x * blockDim.x + threadIdx.x;
    const int grp  = gid >> 3;           // 8-lane group
    const int lane = gid & 7;
    if (grp >= half) return;

    const int  pt0 = grp;
    const int  pt1 = grp + half;
    const bool hiX = (lane >= 4);

    // coords (broadcast across the 8 lanes of each group)
    const float a0 = __ldg(x + (size_t)pt0 * 3 + 0);
    const float a1 = __ldg(x + (size_t)pt0 * 3 + 1);
    const float a2 = __ldg(x + (size_t)pt0 * 3 + 2);
    const float b0 = __ldg(x + (size_t)pt1 * 3 + 0);
    const float b1 = __ldg(x + (size_t)pt1 * 3 + 1);
    const float b2 = __ldg(x + (size_t)pt1 * 3 + 2);

    const float gxsA[3] = { a0, a0, a1 };
    const float gysA[3] = { a1, a2, a2 };
    const float gxsB[3] = { b0, b0, b1 };
    const float gysB[3] = { b1, b2, b2 };

    float acc0[8], acc1[8];
    #pragma unroll
    for (int i = 0; i < 8; ++i) { acc0[i] = 0.f; acc1[i] = 0.f; }

    const __half* Tl = g_Th + (size_t)lane * 8;
    #pragma unroll
    for (int p = 0; p < 3; ++p) {
        const __half* Tp = Tl + (size_t)p * (RES * RES * CFEAT);
        plane_sample(acc0, Tp, gxsA[p], gysA[p], hiX);
        plane_sample(acc1, Tp, gxsB[p], gysB[p], hiX);
    }

    // Combine x0/x1 halves (lanes l and l^4 hold partials for channel group l&3)
    #pragma unroll
    for (int i = 0; i < 8; ++i) {
        acc0[i] += __shfl_xor_sync(0xffffffff, acc0[i], 4);
        acc1[i] += __shfl_xor_sync(0xffffffff, acc1[i], 4);
    }

    const int g = lane & 3;
    const int off = g * 8 + (hiX ? 4 : 0);
    float4 v0 = hiX ? make_float4(acc0[4], acc0[5], acc0[6], acc0[7])
                    : make_float4(acc0[0], acc0[1], acc0[2], acc0[3]);
    float4 v1 = hiX ? make_float4(acc1[4], acc1[5], acc1[6], acc1[7])
                    : make_float4(acc1[0], acc1[1], acc1[2], acc1[3]);
    __stwt(reinterpret_cast<float4*>(out + (size_t)pt0 * CFEAT + off), v0);
    __stwt(reinterpret_cast<float4*>(out + (size_t)pt1 * CFEAT + off), v1);
}

// ---------------------------------------------------------------------------
extern "C" void kernel_launch(void* const* d_in, const int* in_sizes, int n_in,
                              void* d_out, int out_size)
{
    const float* x_in  = (const float*)d_in[0];   // [N, 3]
    const float* c_mat = (const float*)d_in[1];   // [3, 32, 512, 512]
    float* out = (float*)d_out;                   // [N, 32]

    const int npts = in_sizes[0] / 3;
    const int half = npts / 2;

    dim3 tg(RES / 32, RES, 3);
    transpose_kernel<<<tg, 256>>>(c_mat);

    const int threads = 256;
    const long long total = (long long)half * 8;
    const int blocks = (int)((total + threads - 1) / threads);
    sample_kernel<<<blocks, threads>>>(x_in, out, half);
}